// round 13
// baseline (speedup 1.0000x reference)
#include <cuda_runtime.h>
#include <cuda_bf16.h>
#include <math.h>

// ---------------------------------------------------------------------------
// Problem constants
// ---------------------------------------------------------------------------
#define NTOK 32          // tokens
#define MDIM 2048
#define HDIM 8192
#define KC   16          // K per smem chunk (elements)
#define PS   20          // fp32 stage row pitch in floats (80B)
#define STAGE_B ((64 + 32) * PS * 4)        // 7680 bytes per stage
#define XOFF_F (64 * PS)                    // X offset within stage (floats)
#define BF_B   9216                         // bf16 hi/lo buffers total
#define BPITCH 24                           // bf16 buffer row pitch (elements)

typedef unsigned long long ull;
typedef unsigned int u32;

__device__ __forceinline__ u32 smem_u32(const void* p) {
    u32 a;
    asm("{ .reg .u64 t; cvta.to.shared.u64 t, %1; cvt.u32.u64 %0, t; }" : "=r"(a) : "l"(p));
    return a;
}
__device__ __forceinline__ void cpa16(u32 dst, const void* src) {
    asm volatile("cp.async.cg.shared.global [%0], [%1], 16;" :: "r"(dst), "l"(src));
}
__device__ __forceinline__ void cp_commit() {
    asm volatile("cp.async.commit_group;" ::: "memory");
}
template<int N>
__device__ __forceinline__ void cp_wait() {
    asm volatile("cp.async.wait_group %0;" :: "n"(N) : "memory");
}
__device__ __forceinline__ void ldsm4(u32& r0, u32& r1, u32& r2, u32& r3, u32 addr) {
    asm volatile("ldmatrix.sync.aligned.m8n8.x4.shared.b16 {%0,%1,%2,%3}, [%4];"
                 : "=r"(r0), "=r"(r1), "=r"(r2), "=r"(r3) : "r"(addr));
}
__device__ __forceinline__ void mma_bf16(float* d, const u32* a, const u32* b) {
    asm volatile(
        "mma.sync.aligned.m16n8k16.row.col.f32.bf16.bf16.f32 "
        "{%0,%1,%2,%3}, {%4,%5,%6,%7}, {%8,%9}, {%0,%1,%2,%3};"
        : "+f"(d[0]), "+f"(d[1]), "+f"(d[2]), "+f"(d[3])
        : "r"(a[0]), "r"(a[1]), "r"(a[2]), "r"(a[3]), "r"(b[0]), "r"(b[1]));
}
__device__ __forceinline__ void sts64(u32 addr, ull v) {
    asm volatile("st.shared.b64 [%0], %1;" :: "r"(addr), "l"(v) : "memory");
}
// pack 4 bf16 (round-nearest) into a ull; also produce bf16 lo residual
__device__ __forceinline__ void split4(const float* v, ull& hi4, ull& lo4) {
    u32 h01, h23, l01, l23;
    __nv_bfloat16 h0 = __float2bfloat16_rn(v[0]);
    __nv_bfloat16 h1 = __float2bfloat16_rn(v[1]);
    __nv_bfloat16 h2 = __float2bfloat16_rn(v[2]);
    __nv_bfloat16 h3 = __float2bfloat16_rn(v[3]);
    __nv_bfloat16 l0 = __float2bfloat16_rn(v[0] - __bfloat162float(h0));
    __nv_bfloat16 l1 = __float2bfloat16_rn(v[1] - __bfloat162float(h1));
    __nv_bfloat16 l2 = __float2bfloat16_rn(v[2] - __bfloat162float(h2));
    __nv_bfloat16 l3 = __float2bfloat16_rn(v[3] - __bfloat162float(h3));
    h01 = (u32)__bfloat16_as_ushort(h0) | ((u32)__bfloat16_as_ushort(h1) << 16);
    h23 = (u32)__bfloat16_as_ushort(h2) | ((u32)__bfloat16_as_ushort(h3) << 16);
    l01 = (u32)__bfloat16_as_ushort(l0) | ((u32)__bfloat16_as_ushort(l1) << 16);
    l23 = (u32)__bfloat16_as_ushort(l2) | ((u32)__bfloat16_as_ushort(l3) << 16);
    asm("mov.b64 %0, {%1,%2};" : "=l"(hi4) : "r"(h01), "r"(h23));
    asm("mov.b64 %0, {%1,%2};" : "=l"(lo4) : "r"(l01), "r"(l23));
}

// ---------------------------------------------------------------------------
// Scratch
// ---------------------------------------------------------------------------
__device__ float g_xcf [NTOK * MDIM];
__device__ float g_s   [NTOK * MDIM];
__device__ float g_v   [NTOK * MDIM];
__device__ float g_vcum[NTOK * MDIM];
__device__ float g_s2  [NTOK * MDIM];
__device__ float g_h   [NTOK * HDIM];
__device__ float g_part[32 * NTOK * MDIM];   // == 8 * NTOK * HDIM  (8 MB)
__device__ float g_bs  [NTOK * 8 * 2];       // per-(row, col-chunk) sum / sumsq

// ---------------------------------------------------------------------------
// reduce_x: x (16,128,512) -> xcf[32][2048]
// ---------------------------------------------------------------------------
__global__ void reduce_x_k(const float* __restrict__ x, float* __restrict__ xcf) {
    int o = blockIdx.x * blockDim.x + threadIdx.x;
    int i = o >> 11, m = o & 2047, b = m >> 4, a = m & 15;
    const float* p = x + a * (128 * 512) + b * 512 + i * 16;
    float s = 0.f;
#pragma unroll
    for (int t = 0; t < 16; ++t) s += p[t];
    xcf[o] = s * (1.f / 16.f);
}

// ---------------------------------------------------------------------------
// HMMA GEMM: cp.async 3-stage fp32 ring (KC=16, prefetch distance 2) ->
// per-chunk convert pass (fp32 smem -> bf16 hi/lo smem, LN fused) ->
// ldmatrix + mma.
// part[slot][32][N] = X[32][Kslice] @ W[Ntile][Kslice]^T
//   XF: 0 raw X | 1 LN1(x) | 2 LN2(x)+x
// CTA: 128 thr / 4 warps. Tile 64 W-rows x 32 tokens; warp w owns rows
// [w*16, w*16+16). 3 mma terms WhXh + WhXl + WlXh.
// grid = (N/64, SK), klen = K/SK (multiple of KC=16).
// ---------------------------------------------------------------------------
template<int XF>
__global__ void __launch_bounds__(128) tgemm_k(
        const float* __restrict__ X, const float* __restrict__ W,
        float* __restrict__ C, int N, int K,
        const float* __restrict__ bsums, const float* __restrict__ lg,
        const float* __restrict__ lb)
{
    __shared__ __align__(16) char raw[3 * STAGE_B + BF_B + (XF ? 2048 : 16)];
    __shared__ float sh_st[NTOK][2];

    const int tid  = threadIdx.x;
    const int wid  = tid >> 5;
    const int lane = tid & 31;
    const u32 sb   = smem_u32(raw);
    const u32 bb   = sb + 3 * STAGE_B;                 // bf16 buffers base
    const u32 WHI = bb, WLO = bb + 3072, XHI = bb + 6144, XLO = bb + 7680;
    float* stg = (float*)raw;                          // epilogue staging
    float* lnb = (float*)(raw + 3 * STAGE_B + BF_B);   // gamma/beta cache

    const int n0   = blockIdx.x * 64;
    const int klen = K / gridDim.y;
    const int kbeg = blockIdx.y * klen;
    const int nch  = klen / KC;

    if (XF) {
        if (tid < 32) {                // finalize LN stats from combine partials
            float S = 0.f, Q = 0.f;
#pragma unroll
            for (int i = 0; i < 8; ++i) {
                S += bsums[(tid * 8 + i) * 2];
                Q += bsums[(tid * 8 + i) * 2 + 1];
            }
            float m = S * (1.f / (float)MDIM);
            float var = Q * (1.f / (float)MDIM) - m * m;
            sh_st[tid][0] = m;
            sh_st[tid][1] = rsqrtf(var + 1e-5f);
        }
        for (int i = tid; i < klen; i += 128) {
            lnb[2 * i]     = lg[kbeg + i];
            lnb[2 * i + 1] = lb[kbeg + i];
        }
    }

    float acc[4][4];
#pragma unroll
    for (int nt = 0; nt < 4; ++nt)
#pragma unroll
        for (int r = 0; r < 4; ++r) acc[nt][r] = 0.f;

    const int lrow = tid >> 2;     // 0..31
    const int lseg = tid & 3;      // 16B segment (4 per 64B row-chunk)

    auto ISSUE = [&](int c) {
        if (c < nch) {
            const int k0 = kbeg + c * KC;
            const u32 base = sb + (u32)(c % 3) * STAGE_B;
#pragma unroll
            for (int p = 0; p < 2; ++p) {               // W: 64 rows x 16 k
                int row = lrow + p * 32;
                cpa16(base + (u32)(row * PS + lseg * 4) * 4,
                      W + (size_t)(n0 + row) * K + k0 + lseg * 4);
            }
            {                                           // X: 32 rows x 16 k
                int row = lrow;
                cpa16(base + (u32)(XOFF_F + row * PS + lseg * 4) * 4,
                      X + (size_t)row * K + k0 + lseg * 4);
            }
        }
        cp_commit();
    };

    ISSUE(0);
    ISSUE(1);

    for (int c = 0; c < nch; ++c) {
        cp_wait<1>();          // stage c landed (G(c+1) may stay pending)
        __syncthreads();       // all warps past chunk c-1's mma reads
        ISSUE(c + 2);          // refill ring slot (c+2)%3 == (c-1)%3 (free)
        // ---- convert pass: fp32 stage -> bf16 hi/lo (pitch BPITCH=24) ----
        const float* S = (const float*)(raw + (c % 3) * STAGE_B);
#pragma unroll
        for (int p = 0; p < 2; ++p) {                  // W
            int row = lrow + p * 32;
            float4 v4 = *(const float4*)(S + row * PS + lseg * 4);
            ull hi4, lo4;
            split4((const float*)&v4, hi4, lo4);
            u32 off = (u32)(row * BPITCH + lseg * 4) * 2;
            sts64(WHI + off, hi4);
            sts64(WLO + off, lo4);
        }
        {                                              // X (fused LN)
            int row = lrow;
            float4 v4 = *(const float4*)(S + XOFF_F + row * PS + lseg * 4);
            float v[4];
            v[0] = v4.x; v[1] = v4.y; v[2] = v4.z; v[3] = v4.w;
            if (XF) {
                float mn = sh_st[row][0], rs = sh_st[row][1];
                int kk = c * KC + lseg * 4;
#pragma unroll
                for (int e = 0; e < 4; ++e) {
                    float xn = (v[e] - mn) * rs * lnb[2 * (kk + e)] + lnb[2 * (kk + e) + 1];
                    v[e] = (XF == 2) ? (xn + v[e]) : xn;
                }
            }
            u32 off = (u32)(row * BPITCH + lseg * 4) * 2;
            ull hi4, lo4;
            split4(v, hi4, lo4);
            sts64(XHI + off, hi4);
            sts64(XLO + off, lo4);
        }
        __syncthreads();
        // ---- compute: 1 K-step x (4 ntiles x 3 terms) mma ----
        {
            const u32 aoff = (u32)((wid * 16 + (lane & 15)) * BPITCH +
                                   (lane >> 4) * 8) * 2;
            u32 ah[4], al[4];
            ldsm4(ah[0], ah[1], ah[2], ah[3], WHI + aoff);
            ldsm4(al[0], al[1], al[2], al[3], WLO + aoff);
            const u32 boff = (u32)(((lane >> 4) * 8 + (lane & 7)) * BPITCH +
                                   ((lane >> 3) & 1) * 8) * 2;
            u32 bh[2][4], bl[2][4];
#pragma unroll
            for (int pr = 0; pr < 2; ++pr) {
                u32 bo = boff + (u32)(pr * 16 * BPITCH) * 2;
                ldsm4(bh[pr][0], bh[pr][1], bh[pr][2], bh[pr][3], XHI + bo);
                ldsm4(bl[pr][0], bl[pr][1], bl[pr][2], bl[pr][3], XLO + bo);
            }
#pragma unroll
            for (int nt = 0; nt < 4; ++nt) {
                const u32* bhp = &bh[nt >> 1][(nt & 1) * 2];
                const u32* blp = &bl[nt >> 1][(nt & 1) * 2];
                mma_bf16(acc[nt], ah, bhp);
                mma_bf16(acc[nt], ah, blp);
                mma_bf16(acc[nt], al, bhp);
            }
        }
    }

    // ---- epilogue: transpose via smem, coalesced global stores ----
    __syncthreads();
    {
        const int g = lane >> 2, t2 = (lane & 3) * 2;
        const int row = wid * 16 + g;
#pragma unroll
        for (int nt = 0; nt < 4; ++nt) {
            int tok = nt * 8 + t2;
            stg[tok * 68 + row]           = acc[nt][0];
            stg[(tok + 1) * 68 + row]     = acc[nt][1];
            stg[tok * 68 + row + 8]       = acc[nt][2];
            stg[(tok + 1) * 68 + row + 8] = acc[nt][3];
        }
    }
    __syncthreads();
    float* Cb = C + (size_t)blockIdx.y * ((size_t)NTOK * N);
    const int tok0 = tid >> 6, col = tid & 63;
#pragma unroll
    for (int t = tok0; t < NTOK; t += 2)
        Cb[(size_t)t * N + n0 + col] = stg[t * 68 + col];
}

// ---------------------------------------------------------------------------
// combine: out[row][c] = sum_p parts[p][row][c] (+ MODE epilogue)
//   0:+bias (+stats) | 1:+pos bias (+stats) | 2:+resid (+stats)
//   3:+bias,GELU | 4: plain
// grid = (N/256, 32), 256 thr.
// ---------------------------------------------------------------------------
template<int SK, int MODE>
__global__ void combine_k(const float* __restrict__ parts, const float* __restrict__ extra,
                          float* __restrict__ outp, float* __restrict__ bsums, int N)
{
    const int row = blockIdx.y;
    const int c   = blockIdx.x * 256 + threadIdx.x;
    const size_t slot = (size_t)NTOK * N;
    const size_t base = (size_t)row * N + c;

    float v = 0.f;
#pragma unroll
    for (int p = 0; p < SK; ++p) v += parts[p * slot + base];

    if (MODE == 0) {
        v += extra[c];
    } else if (MODE == 1) {
        float iv  = exp2f(-(float)(c & ~1) * 0.012976281620653759f);
        float ang = (float)row * iv;
        v += (c & 1) ? cosf(ang) : sinf(ang);
    } else if (MODE == 2) {
        v += extra[base];
    } else if (MODE == 3) {
        v += extra[c];
        v = 0.5f * v * (1.f + erff(v * 0.70710678118f));
    }
    outp[base] = v;

    if (MODE <= 2) {
        float s = v, q = v * v;
#pragma unroll
        for (int off = 16; off; off >>= 1) {
            s += __shfl_down_sync(0xffffffffu, s, off);
            q += __shfl_down_sync(0xffffffffu, q, off);
        }
        __shared__ float rs[8], rq[8];
        if ((threadIdx.x & 31) == 0) { rs[threadIdx.x >> 5] = s; rq[threadIdx.x >> 5] = q; }
        __syncthreads();
        if (threadIdx.x == 0) {
            float S = 0.f, Q = 0.f;
#pragma unroll
            for (int i = 0; i < 8; ++i) { S += rs[i]; Q += rq[i]; }
            bsums[(row * gridDim.x + blockIdx.x) * 2]     = S;
            bsums[(row * gridDim.x + blockIdx.x) * 2 + 1] = Q;
        }
    }
}

// token prefix-sum: vcum[i][k] = sum_{j<=i} V[j][k]
__global__ void prefix_k(const float* __restrict__ V, float* __restrict__ vc) {
    int k = blockIdx.x * 256 + threadIdx.x;
    float acc = 0.f;
#pragma unroll
    for (int i = 0; i < NTOK; ++i) {
        acc += V[i * MDIM + k];
        vc[i * MDIM + k] = acc;
    }
}

// ---------------------------------------------------------------------------
// launch
// ---------------------------------------------------------------------------
extern "C" void kernel_launch(void* const* d_in, const int* in_sizes, int n_in,
                              void* d_out, int out_size)
{
    const float* x      = (const float*)d_in[0];
    const float* weight = (const float*)d_in[1];
    // d_in[2]=Wq, d_in[3]=Wk unused (softmax over singleton axis == 1)
    const float* Wv     = (const float*)d_in[4];
    const float* Wo     = (const float*)d_in[5];
    const float* ln1g   = (const float*)d_in[6];
    const float* ln1b   = (const float*)d_in[7];
    const float* ln2g   = (const float*)d_in[8];
    const float* ln2b   = (const float*)d_in[9];
    const float* fc1w   = (const float*)d_in[10];
    const float* fc1b   = (const float*)d_in[11];
    const float* fc2w   = (const float*)d_in[12];
    const float* fc2b   = (const float*)d_in[13];
    float* out = (float*)d_out;

    float *xcf, *sbuf, *vbuf, *vcum, *s2, *hbuf, *part, *bs;
    cudaGetSymbolAddress((void**)&xcf,  g_xcf);
    cudaGetSymbolAddress((void**)&sbuf, g_s);
    cudaGetSymbolAddress((void**)&vbuf, g_v);
    cudaGetSymbolAddress((void**)&vcum, g_vcum);
    cudaGetSymbolAddress((void**)&s2,   g_s2);
    cudaGetSymbolAddress((void**)&hbuf, g_h);
    cudaGetSymbolAddress((void**)&part, g_part);
    cudaGetSymbolAddress((void**)&bs,   g_bs);

    const size_t WSLAB = (size_t)MDIM * MDIM;

    reduce_x_k<<<256, 256>>>(x, xcf);

    // s0 = xcf @ weight^T ; +pos bias ; LN1 stat partials
    tgemm_k<0><<<dim3(32, 32), 128>>>(xcf, weight, part, MDIM, MDIM, 0, 0, 0);
    combine_k<32, 1><<<dim3(8, NTOK), 256>>>(part, nullptr, sbuf, bs, MDIM);

    for (int a = 0; a < 3; ++a) {
        // V = LN1(s) @ Wv[a]^T ; combine ; prefix -> vcum
        tgemm_k<1><<<dim3(32, 32), 128>>>(sbuf, Wv + a * WSLAB, part, MDIM, MDIM,
                                          bs, ln1g, ln1b);
        combine_k<32, 4><<<dim3(8, NTOK), 256>>>(part, nullptr, vbuf, nullptr, MDIM);
        prefix_k<<<8, 256>>>(vbuf, vcum);
        // s2 = vcum @ Wo[a]^T + s ; LN2 stat partials
        tgemm_k<0><<<dim3(32, 32), 128>>>(vcum, Wo + a * WSLAB, part, MDIM, MDIM, 0, 0, 0);
        combine_k<32, 2><<<dim3(8, NTOK), 256>>>(part, sbuf, s2, bs, MDIM);
        // h = gelu( (LN2(s2)+s2) @ fc1^T + b1 )
        tgemm_k<2><<<dim3(128, 8), 128>>>(s2, fc1w, part, HDIM, MDIM, bs, ln2g, ln2b);
        combine_k<8, 3><<<dim3(32, NTOK), 256>>>(part, fc1b, hbuf, nullptr, HDIM);
        // s_next = h @ fc2^T + b2 ; LN1 stat partials for next block
        tgemm_k<0><<<dim3(32, 32), 128>>>(hbuf, fc2w, part, MDIM, HDIM, 0, 0, 0);
        combine_k<32, 0><<<dim3(8, NTOK), 256>>>(part, fc2b, (a == 2) ? out : sbuf, bs, MDIM);
    }
    (void)in_sizes; (void)n_in; (void)out_size;
}

// round 14
// speedup vs baseline: 1.2753x; 1.2753x over previous
#include <cuda_runtime.h>
#include <cuda_bf16.h>
#include <math.h>

// ---------------------------------------------------------------------------
// Problem constants
// ---------------------------------------------------------------------------
#define NTOK 32          // tokens
#define MDIM 2048
#define HDIM 8192
#define KC   32          // K per chunk (elements)
#define BUF_B 15360      // one bf16 hi/lo buffer set (pitch-40 layout)

typedef unsigned long long ull;
typedef unsigned int u32;

__device__ __forceinline__ u32 smem_u32(const void* p) {
    u32 a;
    asm("{ .reg .u64 t; cvta.to.shared.u64 t, %1; cvt.u32.u64 %0, t; }" : "=r"(a) : "l"(p));
    return a;
}
__device__ __forceinline__ void ldsm4(u32& r0, u32& r1, u32& r2, u32& r3, u32 addr) {
    asm volatile("ldmatrix.sync.aligned.m8n8.x4.shared.b16 {%0,%1,%2,%3}, [%4];"
                 : "=r"(r0), "=r"(r1), "=r"(r2), "=r"(r3) : "r"(addr));
}
__device__ __forceinline__ void mma_bf16(float* d, const u32* a, const u32* b) {
    asm volatile(
        "mma.sync.aligned.m16n8k16.row.col.f32.bf16.bf16.f32 "
        "{%0,%1,%2,%3}, {%4,%5,%6,%7}, {%8,%9}, {%0,%1,%2,%3};"
        : "+f"(d[0]), "+f"(d[1]), "+f"(d[2]), "+f"(d[3])
        : "r"(a[0]), "r"(a[1]), "r"(a[2]), "r"(a[3]), "r"(b[0]), "r"(b[1]));
}
__device__ __forceinline__ void sts64(u32 addr, ull v) {
    asm volatile("st.shared.b64 [%0], %1;" :: "r"(addr), "l"(v) : "memory");
}
// pack 4 bf16 (round-nearest) into a ull; also produce bf16 lo residual
__device__ __forceinline__ void split4(const float* v, ull& hi4, ull& lo4) {
    u32 h01, h23, l01, l23;
    __nv_bfloat16 h0 = __float2bfloat16_rn(v[0]);
    __nv_bfloat16 h1 = __float2bfloat16_rn(v[1]);
    __nv_bfloat16 h2 = __float2bfloat16_rn(v[2]);
    __nv_bfloat16 h3 = __float2bfloat16_rn(v[3]);
    __nv_bfloat16 l0 = __float2bfloat16_rn(v[0] - __bfloat162float(h0));
    __nv_bfloat16 l1 = __float2bfloat16_rn(v[1] - __bfloat162float(h1));
    __nv_bfloat16 l2 = __float2bfloat16_rn(v[2] - __bfloat162float(h2));
    __nv_bfloat16 l3 = __float2bfloat16_rn(v[3] - __bfloat162float(h3));
    h01 = (u32)__bfloat16_as_ushort(h0) | ((u32)__bfloat16_as_ushort(h1) << 16);
    h23 = (u32)__bfloat16_as_ushort(h2) | ((u32)__bfloat16_as_ushort(h3) << 16);
    l01 = (u32)__bfloat16_as_ushort(l0) | ((u32)__bfloat16_as_ushort(l1) << 16);
    l23 = (u32)__bfloat16_as_ushort(l2) | ((u32)__bfloat16_as_ushort(l3) << 16);
    asm("mov.b64 %0, {%1,%2};" : "=l"(hi4) : "r"(h01), "r"(h23));
    asm("mov.b64 %0, {%1,%2};" : "=l"(lo4) : "r"(l01), "r"(l23));
}

// ---------------------------------------------------------------------------
// Scratch
// ---------------------------------------------------------------------------
__device__ float g_xcf [NTOK * MDIM];
__device__ float g_s   [NTOK * MDIM];
__device__ float g_v   [NTOK * MDIM];
__device__ float g_vcum[NTOK * MDIM];
__device__ float g_s2  [NTOK * MDIM];
__device__ float g_h   [NTOK * HDIM];
__device__ float g_part[16 * NTOK * MDIM];   // == 4 * NTOK * HDIM  (4 MB)
__device__ float g_bs  [NTOK * 8 * 2];       // per-(row, col-chunk) sum / sumsq

// ---------------------------------------------------------------------------
// reduce_x: x (16,128,512) -> xcf[32][2048]
// ---------------------------------------------------------------------------
__global__ void reduce_x_k(const float* __restrict__ x, float* __restrict__ xcf) {
    int o = blockIdx.x * blockDim.x + threadIdx.x;
    int i = o >> 11, m = o & 2047, b = m >> 4, a = m & 15;
    const float* p = x + a * (128 * 512) + b * 512 + i * 16;
    float s = 0.f;
#pragma unroll
    for (int t = 0; t < 16; ++t) s += p[t];
    xcf[o] = s * (1.f / 16.f);
}

// ---------------------------------------------------------------------------
// HMMA GEMM (R9 datapath + 2-deep register prefetch + double-buffered bf16
// smem, 1 sync per chunk):
//   part[slot][32][N] = X[32][Kslice] @ W[Ntile][Kslice]^T
//   XF: 0 raw X | 1 LN1(x) | 2 LN2(x)+x  (stats finalized from bs in-kernel)
// CTA: 128 thr / 4 warps. Tile 64 W-rows x 32 tokens; warp w owns rows
// [w*16, w*16+16). 3 mma terms WhXh + WhXl + WlXh.
// grid = (N/64, SK), klen = K/SK (multiple of 2*KC=64).
// ---------------------------------------------------------------------------
template<int XF>
__global__ void __launch_bounds__(128) tgemm_k(
        const float* __restrict__ X, const float* __restrict__ W,
        float* __restrict__ C, int N, int K,
        const float* __restrict__ bsums, const float* __restrict__ lg,
        const float* __restrict__ lb)
{
    __shared__ __align__(16) char raw[2 * BUF_B];
    __shared__ float sh_st[NTOK][2];

    const int tid  = threadIdx.x;
    const int wid  = tid >> 5;
    const int lane = tid & 31;
    const u32 sb   = smem_u32(raw);
    float* stg = (float*)raw;

    const int n0   = blockIdx.x * 64;
    const int klen = K / gridDim.y;
    const int kbeg = blockIdx.y * klen;
    const int nch  = klen / KC;

    if (XF && tid < 32) {                  // finalize LN stats from combine partials
        float S = 0.f, Q = 0.f;
#pragma unroll
        for (int i = 0; i < 8; ++i) {
            S += bsums[(tid * 8 + i) * 2];
            Q += bsums[(tid * 8 + i) * 2 + 1];
        }
        float m = S * (1.f / (float)MDIM);
        float var = Q * (1.f / (float)MDIM) - m * m;
        sh_st[tid][0] = m;
        sh_st[tid][1] = rsqrtf(var + 1e-5f);
    }

    float acc[4][4];
#pragma unroll
    for (int nt = 0; nt < 4; ++nt)
#pragma unroll
        for (int r = 0; r < 4; ++r) acc[nt][r] = 0.f;

    const int lrow = tid >> 3;     // 0..15
    const int lc4  = tid & 7;

    auto LOAD = [&](int k0, float4* wb, float4* xb) {
#pragma unroll
        for (int p = 0; p < 4; ++p)
            wb[p] = *(const float4*)(W + (size_t)(n0 + lrow + p * 16) * K + k0 + lc4 * 4);
#pragma unroll
        for (int p = 0; p < 2; ++p)
            xb[p] = *(const float4*)(X + (size_t)(lrow + p * 16) * K + k0 + lc4 * 4);
    };

    auto CONV = [&](u32 bbase, const float4* wb, const float4* xb, int k0) {
        const u32 WHI = bbase, WLO = bbase + 5120, XHI = bbase + 10240, XLO = bbase + 12800;
#pragma unroll
        for (int p = 0; p < 4; ++p) {
            int row = lrow + p * 16;
            u32 off = (u32)(row * 40 + lc4 * 4) * 2;
            ull hi4, lo4;
            split4((const float*)&wb[p], hi4, lo4);
            sts64(WHI + off, hi4);
            sts64(WLO + off, lo4);
        }
#pragma unroll
        for (int p = 0; p < 2; ++p) {
            int row = lrow + p * 16;
            float v[4];
            v[0] = xb[p].x; v[1] = xb[p].y; v[2] = xb[p].z; v[3] = xb[p].w;
            if (XF) {
                float mn = sh_st[row][0], rs = sh_st[row][1];
#pragma unroll
                for (int e = 0; e < 4; ++e) {
                    float xn = (v[e] - mn) * rs * lg[k0 + lc4 * 4 + e] + lb[k0 + lc4 * 4 + e];
                    v[e] = (XF == 2) ? (xn + v[e]) : xn;
                }
            }
            u32 off = (u32)(row * 40 + lc4 * 4) * 2;
            ull hi4, lo4;
            split4(v, hi4, lo4);
            sts64(XHI + off, hi4);
            sts64(XLO + off, lo4);
        }
    };

    auto MMAC = [&](u32 bbase) {
        const u32 WHI = bbase, WLO = bbase + 5120, XHI = bbase + 10240, XLO = bbase + 12800;
#pragma unroll
        for (int ks = 0; ks < 2; ++ks) {
            const u32 aoff = (u32)((wid * 16 + (lane & 15)) * 40 +
                                   ks * 16 + (lane >> 4) * 8) * 2;
            u32 ah[4], al[4];
            ldsm4(ah[0], ah[1], ah[2], ah[3], WHI + aoff);
            ldsm4(al[0], al[1], al[2], al[3], WLO + aoff);
            const u32 boff = (u32)(((lane >> 4) * 8 + (lane & 7)) * 40 +
                                   ks * 16 + ((lane >> 3) & 1) * 8) * 2;
            u32 bh[2][4], bl[2][4];
#pragma unroll
            for (int pr = 0; pr < 2; ++pr) {
                u32 bo = boff + (u32)(pr * 16 * 40) * 2;
                ldsm4(bh[pr][0], bh[pr][1], bh[pr][2], bh[pr][3], XHI + bo);
                ldsm4(bl[pr][0], bl[pr][1], bl[pr][2], bl[pr][3], XLO + bo);
            }
#pragma unroll
            for (int nt = 0; nt < 4; ++nt) {
                const u32* bhp = &bh[nt >> 1][(nt & 1) * 2];
                const u32* blp = &bl[nt >> 1][(nt & 1) * 2];
                mma_bf16(acc[nt], ah, bhp);
                mma_bf16(acc[nt], ah, blp);
                mma_bf16(acc[nt], al, bhp);
            }
        }
    };

    float4 wA[4], xA[2], wB[4], xB[2];
    LOAD(kbeg, wA, xA);
    LOAD(kbeg + KC, wB, xB);
    __syncthreads();                 // sh_st visible (XF); aligns warps at start

    for (int c = 0; c < nch; c += 2) {
        // ---- chunk c : buffer 0, regs A ----
        CONV(sb, wA, xA, kbeg + c * KC);
        __syncthreads();
        if (c + 2 < nch) LOAD(kbeg + (c + 2) * KC, wA, xA);
        MMAC(sb);
        // ---- chunk c+1 : buffer 1, regs B ----
        CONV(sb + BUF_B, wB, xB, kbeg + (c + 1) * KC);
        __syncthreads();
        if (c + 3 < nch) LOAD(kbeg + (c + 3) * KC, wB, xB);
        MMAC(sb + BUF_B);
    }

    // ---- epilogue: transpose via smem, coalesced global stores ----
    __syncthreads();
    {
        const int g = lane >> 2, t2 = (lane & 3) * 2;
        const int row = wid * 16 + g;
#pragma unroll
        for (int nt = 0; nt < 4; ++nt) {
            int tok = nt * 8 + t2;
            stg[tok * 68 + row]           = acc[nt][0];
            stg[(tok + 1) * 68 + row]     = acc[nt][1];
            stg[tok * 68 + row + 8]       = acc[nt][2];
            stg[(tok + 1) * 68 + row + 8] = acc[nt][3];
        }
    }
    __syncthreads();
    float* Cb = C + (size_t)blockIdx.y * ((size_t)NTOK * N);
    const int tok0 = tid >> 6, col = tid & 63;
#pragma unroll
    for (int t = tok0; t < NTOK; t += 2)
        Cb[(size_t)t * N + n0 + col] = stg[t * 68 + col];
}

// ---------------------------------------------------------------------------
// combine: out[row][c] = sum_p parts[p][row][c] (+ MODE epilogue)
//   0:+bias (+stats) | 1:+pos bias (+stats) | 2:+resid (+stats)
//   3:+bias,GELU | 4: plain
// grid = (N/256, 32), 256 thr.
// ---------------------------------------------------------------------------
template<int SK, int MODE>
__global__ void combine_k(const float* __restrict__ parts, const float* __restrict__ extra,
                          float* __restrict__ outp, float* __restrict__ bsums, int N)
{
    const int row = blockIdx.y;
    const int c   = blockIdx.x * 256 + threadIdx.x;
    const size_t slot = (size_t)NTOK * N;
    const size_t base = (size_t)row * N + c;

    float v = 0.f;
#pragma unroll
    for (int p = 0; p < SK; ++p) v += parts[p * slot + base];

    if (MODE == 0) {
        v += extra[c];
    } else if (MODE == 1) {
        float iv  = exp2f(-(float)(c & ~1) * 0.012976281620653759f);
        float ang = (float)row * iv;
        v += (c & 1) ? cosf(ang) : sinf(ang);
    } else if (MODE == 2) {
        v += extra[base];
    } else if (MODE == 3) {
        v += extra[c];
        v = 0.5f * v * (1.f + erff(v * 0.70710678118f));
    }
    outp[base] = v;

    if (MODE <= 2) {
        float s = v, q = v * v;
#pragma unroll
        for (int off = 16; off; off >>= 1) {
            s += __shfl_down_sync(0xffffffffu, s, off);
            q += __shfl_down_sync(0xffffffffu, q, off);
        }
        __shared__ float rs[8], rq[8];
        if ((threadIdx.x & 31) == 0) { rs[threadIdx.x >> 5] = s; rq[threadIdx.x >> 5] = q; }
        __syncthreads();
        if (threadIdx.x == 0) {
            float S = 0.f, Q = 0.f;
#pragma unroll
            for (int i = 0; i < 8; ++i) { S += rs[i]; Q += rq[i]; }
            bsums[(row * gridDim.x + blockIdx.x) * 2]     = S;
            bsums[(row * gridDim.x + blockIdx.x) * 2 + 1] = Q;
        }
    }
}

// token prefix-sum: vcum[i][k] = sum_{j<=i} V[j][k]
__global__ void prefix_k(const float* __restrict__ V, float* __restrict__ vc) {
    int k = blockIdx.x * 256 + threadIdx.x;
    float acc = 0.f;
#pragma unroll
    for (int i = 0; i < NTOK; ++i) {
        acc += V[i * MDIM + k];
        vc[i * MDIM + k] = acc;
    }
}

// ---------------------------------------------------------------------------
// launch
// ---------------------------------------------------------------------------
extern "C" void kernel_launch(void* const* d_in, const int* in_sizes, int n_in,
                              void* d_out, int out_size)
{
    const float* x      = (const float*)d_in[0];
    const float* weight = (const float*)d_in[1];
    // d_in[2]=Wq, d_in[3]=Wk unused (softmax over singleton axis == 1)
    const float* Wv     = (const float*)d_in[4];
    const float* Wo     = (const float*)d_in[5];
    const float* ln1g   = (const float*)d_in[6];
    const float* ln1b   = (const float*)d_in[7];
    const float* ln2g   = (const float*)d_in[8];
    const float* ln2b   = (const float*)d_in[9];
    const float* fc1w   = (const float*)d_in[10];
    const float* fc1b   = (const float*)d_in[11];
    const float* fc2w   = (const float*)d_in[12];
    const float* fc2b   = (const float*)d_in[13];
    float* out = (float*)d_out;

    float *xcf, *sbuf, *vbuf, *vcum, *s2, *hbuf, *part, *bs;
    cudaGetSymbolAddress((void**)&xcf,  g_xcf);
    cudaGetSymbolAddress((void**)&sbuf, g_s);
    cudaGetSymbolAddress((void**)&vbuf, g_v);
    cudaGetSymbolAddress((void**)&vcum, g_vcum);
    cudaGetSymbolAddress((void**)&s2,   g_s2);
    cudaGetSymbolAddress((void**)&hbuf, g_h);
    cudaGetSymbolAddress((void**)&part, g_part);
    cudaGetSymbolAddress((void**)&bs,   g_bs);

    const size_t WSLAB = (size_t)MDIM * MDIM;

    reduce_x_k<<<256, 256>>>(x, xcf);

    // s0 = xcf @ weight^T ; +pos bias ; LN1 stat partials
    tgemm_k<0><<<dim3(32, 16), 128>>>(xcf, weight, part, MDIM, MDIM, 0, 0, 0);
    combine_k<16, 1><<<dim3(8, NTOK), 256>>>(part, nullptr, sbuf, bs, MDIM);

    for (int a = 0; a < 3; ++a) {
        // V = LN1(s) @ Wv[a]^T ; combine ; prefix -> vcum
        tgemm_k<1><<<dim3(32, 16), 128>>>(sbuf, Wv + a * WSLAB, part, MDIM, MDIM,
                                          bs, ln1g, ln1b);
        combine_k<16, 4><<<dim3(8, NTOK), 256>>>(part, nullptr, vbuf, nullptr, MDIM);
        prefix_k<<<8, 256>>>(vbuf, vcum);
        // s2 = vcum @ Wo[a]^T + s ; LN2 stat partials
        tgemm_k<0><<<dim3(32, 16), 128>>>(vcum, Wo + a * WSLAB, part, MDIM, MDIM, 0, 0, 0);
        combine_k<16, 2><<<dim3(8, NTOK), 256>>>(part, sbuf, s2, bs, MDIM);
        // h = gelu( (LN2(s2)+s2) @ fc1^T + b1 )
        tgemm_k<2><<<dim3(128, 4), 128>>>(s2, fc1w, part, HDIM, MDIM, bs, ln2g, ln2b);
        combine_k<4, 3><<<dim3(32, NTOK), 256>>>(part, fc1b, hbuf, nullptr, HDIM);
        // s_next = h @ fc2^T + b2 ; LN1 stat partials for next block
        tgemm_k<0><<<dim3(32, 16), 128>>>(hbuf, fc2w, part, MDIM, HDIM, 0, 0, 0);
        combine_k<16, 0><<<dim3(8, NTOK), 256>>>(part, fc2b, (a == 2) ? out : sbuf, bs, MDIM);
    }
    (void)in_sizes; (void)n_in; (void)out_size;
}